// round 9
// baseline (speedup 1.0000x reference)
#include <cuda_runtime.h>
#include <cuda_bf16.h>
#include <cstdint>
#include <math.h>

// ---------------------------------------------------------------------------
// Swin Transformer encoder layer, GB300 round-9:
// R6 structure (tf32 mma.sync, 128x128 CTA, BK=16, 4-stage cp.async)
// with 3 CTAs/SM for barrier-latency hiding.
// ---------------------------------------------------------------------------

#define T_TOK   65536
#define E_DIM   512
#define QKV_N   1536
#define DFF_N   2048
#define NWIN    1024
#define NH_     16
#define HD_     32

__device__ float g_qkv[(size_t)T_TOK * QKV_N];
__device__ float g_attn[(size_t)T_TOK * E_DIM];
__device__ float g_t0[(size_t)T_TOK * E_DIM];
__device__ float g_z[(size_t)T_TOK * E_DIM];
__device__ float g_h[(size_t)T_TOK * DFF_N];

__device__ __forceinline__ int to_win_row(int m) {
    int b = m >> 14, p = m & 16383;
    int r = p >> 7, c = p & 127;
    int win = (b << 8) + ((r >> 3) << 4) + (c >> 3);
    int n   = ((r & 7) << 3) + (c & 7);
    return (win << 6) + n;
}
__device__ __forceinline__ int from_win_row(int m) {
    int win = m >> 6, n = m & 63;
    int b  = win >> 8, wi = win & 255;
    int wr = wi >> 4,  wc = wi & 15;
    int r = (wr << 3) + (n >> 3);
    int c = (wc << 3) + (n & 7);
    return (b << 14) + (r << 7) + c;
}

__device__ __forceinline__ void mma_tf32(float c[4], const uint32_t a[4], const uint32_t b[2]) {
    asm volatile(
        "mma.sync.aligned.m16n8k8.row.col.f32.tf32.tf32.f32 "
        "{%0,%1,%2,%3},{%4,%5,%6,%7},{%8,%9},{%0,%1,%2,%3};\n"
        : "+f"(c[0]), "+f"(c[1]), "+f"(c[2]), "+f"(c[3])
        : "r"(a[0]), "r"(a[1]), "r"(a[2]), "r"(a[3]), "r"(b[0]), "r"(b[1]));
}

__device__ __forceinline__ void ldsm4(uint32_t& r0, uint32_t& r1, uint32_t& r2, uint32_t& r3,
                                      uint32_t addr) {
    asm volatile("ldmatrix.sync.aligned.m8n8.x4.shared.b16 {%0,%1,%2,%3}, [%4];"
                 : "=r"(r0), "=r"(r1), "=r"(r2), "=r"(r3) : "r"(addr));
}

__device__ __forceinline__ void cpasync16(uint32_t dst, const float* src) {
    asm volatile("cp.async.cg.shared.global [%0], [%1], 16;" :: "r"(dst), "l"(src));
}
__device__ __forceinline__ void cp_commit() {
    asm volatile("cp.async.commit_group;" ::: "memory");
}
template <int N>
__device__ __forceinline__ void cp_wait() {
    asm volatile("cp.async.wait_group %0;" :: "n"(N) : "memory");
}

// ---------------------------------------------------------------------------
// TF32 NT GEMM: C[m][n] = sum_k A[m][k]*B[n][k] + bias[n].
// Block 128x128, BK=16, 256 threads (8 warps as 2x4), warp tile 64x32.
// Smem: k-major 128x16 tiles, XOR swizzle (chunk ^= (row>>1)&3); 4-stage
// cp.async ring; ldmatrix.x4.b16 fragment reads; raw fp32 bits to tf32 mma.
// EPI: 0 bias, 1 bias+relu.  PERM: 0 none, 1 to_win, 2 from_win.
// ---------------------------------------------------------------------------
#define STAGES 4
#define GSM_BYTES (STAGES * 8192 * 2)

template <int EPI, int PERM>
__global__ void __launch_bounds__(256, 3) gemm_tf32(
    const float* __restrict__ A, const float* __restrict__ B,
    const float* __restrict__ bias, float* __restrict__ C,
    int M, int N, int K)
{
    extern __shared__ __align__(128) uint32_t smem[];
    const uint32_t asb = (uint32_t)__cvta_generic_to_shared(smem);
    const uint32_t bsb = asb + STAGES * 8192;

    const int tid  = threadIdx.x;
    const int lane = tid & 31;
    const int warp = tid >> 5;
    const int wr = warp >> 2;
    const int wc = warp & 3;
    const int bm = blockIdx.y << 7;
    const int bn = blockIdx.x << 7;

    const int lrow = tid >> 2;
    const int lk   = (tid & 3) << 2;
    const int sw   = (((lk >> 2) ^ ((lrow >> 1) & 3)) << 2);
    const uint32_t aoff0 = (uint32_t)(lrow * 16 + sw) * 4u;
    const uint32_t aoff1 = aoff0 + 64 * 16 * 4;

    const float* aP0 = A + (size_t)(bm + lrow) * K + lk;
    const float* aP1 = A + (size_t)(bm + lrow + 64) * K + lk;
    const float* bP0 = B + (size_t)(bn + lrow) * K + lk;
    const float* bP1 = B + (size_t)(bn + lrow + 64) * K + lk;

    const int lm   = (lane & 7) + (((lane >> 3) & 1) << 3);
    const int ahik = lane >> 4;
    const int amsw = (lm >> 1) & 3;
    const int brow = lane & 7;
    const int bnt2 = (lane >> 4) & 1;
    const int bhik = (lane >> 3) & 1;
    const int bmsw = (brow >> 1) & 3;

    float acc[4][4][4];
#pragma unroll
    for (int i = 0; i < 4; i++)
#pragma unroll
        for (int j = 0; j < 4; j++)
#pragma unroll
            for (int v = 0; v < 4; v++) acc[i][j][v] = 0.f;

    const int ntiles = K >> 4;

#pragma unroll
    for (int s = 0; s < STAGES - 1; s++) {
        const int kk = s << 4;
        const uint32_t sa = asb + s * 8192;
        const uint32_t sb = bsb + s * 8192;
        cpasync16(sa + aoff0, aP0 + kk);
        cpasync16(sa + aoff1, aP1 + kk);
        cpasync16(sb + aoff0, bP0 + kk);
        cpasync16(sb + aoff1, bP1 + kk);
        cp_commit();
    }

    for (int t = 0; t < ntiles; t++) {
        cp_wait<STAGES - 2>();
        __syncthreads();

        if (t + STAGES - 1 < ntiles) {
            const int s = (t + STAGES - 1) & (STAGES - 1);
            const int kk = (t + STAGES - 1) << 4;
            const uint32_t sa = asb + s * 8192;
            const uint32_t sb = bsb + s * 8192;
            cpasync16(sa + aoff0, aP0 + kk);
            cpasync16(sa + aoff1, aP1 + kk);
            cpasync16(sb + aoff0, bP0 + kk);
            cpasync16(sb + aoff1, bP1 + kk);
            cp_commit();
        }

        const int cur = t & (STAGES - 1);
        const uint32_t abuf = asb + cur * 8192;
        const uint32_t bbuf = bsb + cur * 8192;
#pragma unroll
        for (int s = 0; s < 2; s++) {
            uint32_t afr[4][4];
#pragma unroll
            for (int i = 0; i < 4; i++) {
                int m = wr * 64 + i * 16 + lm;
                int chunk = (s * 2 + ahik) ^ amsw;
                ldsm4(afr[i][0], afr[i][1], afr[i][2], afr[i][3],
                      abuf + (uint32_t)(m * 16 + chunk * 4) * 4u);
            }
            uint32_t bfr[4][2];
#pragma unroll
            for (int jj = 0; jj < 2; jj++) {
                int ntile = wc * 4 + 2 * jj + bnt2;
                int n = ntile * 8 + brow;
                int chunk = (s * 2 + bhik) ^ bmsw;
                ldsm4(bfr[2 * jj][0], bfr[2 * jj][1], bfr[2 * jj + 1][0], bfr[2 * jj + 1][1],
                      bbuf + (uint32_t)(n * 16 + chunk * 4) * 4u);
            }
#pragma unroll
            for (int i = 0; i < 4; i++)
#pragma unroll
                for (int j = 0; j < 4; j++)
                    mma_tf32(acc[i][j], afr[i], bfr[j]);
        }
    }

    // epilogue
    const int r  = lane >> 2;
    const int cc = (lane & 3) << 1;
#pragma unroll
    for (int i = 0; i < 4; i++) {
        int row0 = bm + wr * 64 + i * 16 + r;
        int row1 = row0 + 8;
        int o0, o1;
        if (PERM == 0)      { o0 = row0;               o1 = row1; }
        else if (PERM == 1) { o0 = to_win_row(row0);   o1 = to_win_row(row1); }
        else                { o0 = from_win_row(row0); o1 = from_win_row(row1); }
#pragma unroll
        for (int j = 0; j < 4; j++) {
            int gn = bn + wc * 32 + j * 8 + cc;
            float b0 = bias[gn], b1 = bias[gn + 1];
            float v00 = acc[i][j][0] + b0, v01 = acc[i][j][1] + b1;
            float v10 = acc[i][j][2] + b0, v11 = acc[i][j][3] + b1;
            if (EPI == 1) {
                v00 = fmaxf(v00, 0.f); v01 = fmaxf(v01, 0.f);
                v10 = fmaxf(v10, 0.f); v11 = fmaxf(v11, 0.f);
            }
            *(float2*)&C[(size_t)o0 * N + gn] = make_float2(v00, v01);
            *(float2*)&C[(size_t)o1 * N + gn] = make_float2(v10, v11);
        }
    }
}

// ---------------------------------------------------------------------------
// Window attention: one block per (window, head). 4x4 register micro-tiles.
// ---------------------------------------------------------------------------
__global__ void __launch_bounds__(256) attn_kernel(
    const float* __restrict__ qkv, const float* __restrict__ pos_emb,
    float* __restrict__ out)
{
    const int win = blockIdx.x;
    const int head = blockIdx.y;
    const int tid = threadIdx.x;

    __shared__ float Qt[32 * 68];
    __shared__ float Kt[32 * 68];
    __shared__ float Vs[64 * 36];
    __shared__ float Pt[64 * 68];
    __shared__ float bias_s[225];

    {
        int n  = tid >> 2;
        int c0 = (tid & 3) << 3;
        size_t base = ((size_t)win * 64 + n) * (size_t)QKV_N + head * HD_ + c0;
        float4 a = *(const float4*)(qkv + base);
        float4 b = *(const float4*)(qkv + base + 4);
        Qt[(c0 + 0) * 68 + n] = a.x; Qt[(c0 + 1) * 68 + n] = a.y;
        Qt[(c0 + 2) * 68 + n] = a.z; Qt[(c0 + 3) * 68 + n] = a.w;
        Qt[(c0 + 4) * 68 + n] = b.x; Qt[(c0 + 5) * 68 + n] = b.y;
        Qt[(c0 + 6) * 68 + n] = b.z; Qt[(c0 + 7) * 68 + n] = b.w;
        a = *(const float4*)(qkv + base + 512);
        b = *(const float4*)(qkv + base + 516);
        Kt[(c0 + 0) * 68 + n] = a.x; Kt[(c0 + 1) * 68 + n] = a.y;
        Kt[(c0 + 2) * 68 + n] = a.z; Kt[(c0 + 3) * 68 + n] = a.w;
        Kt[(c0 + 4) * 68 + n] = b.x; Kt[(c0 + 5) * 68 + n] = b.y;
        Kt[(c0 + 6) * 68 + n] = b.z; Kt[(c0 + 7) * 68 + n] = b.w;
        a = *(const float4*)(qkv + base + 1024);
        b = *(const float4*)(qkv + base + 1028);
        *(float4*)&Vs[n * 36 + c0]     = a;
        *(float4*)&Vs[n * 36 + c0 + 4] = b;
    }
    if (tid < 225) bias_s[tid] = pos_emb[tid];
    __syncthreads();

    const int tq = tid >> 4;
    const int tk = tid & 15;

    float s[4][4];
#pragma unroll
    for (int a = 0; a < 4; a++)
#pragma unroll
        for (int b = 0; b < 4; b++) s[a][b] = 0.f;

#pragma unroll 8
    for (int d = 0; d < 32; d++) {
        float4 qf = *(const float4*)&Qt[d * 68 + tq * 4];
        float4 kf = *(const float4*)&Kt[d * 68 + tk * 4];
        const float* qa = (const float*)&qf;
        const float* ka = (const float*)&kf;
#pragma unroll
        for (int a = 0; a < 4; a++)
#pragma unroll
            for (int b = 0; b < 4; b++)
                s[a][b] = fmaf(qa[a], ka[b], s[a][b]);
    }

    const float scl = 0.17677669529663687f;
#pragma unroll
    for (int a = 0; a < 4; a++) {
        int q = tq * 4 + a, qh = q >> 3, qw = q & 7;
#pragma unroll
        for (int b = 0; b < 4; b++) {
            int k = tk * 4 + b, kh = k >> 3, kw = k & 7;
            s[a][b] = s[a][b] * scl + bias_s[(kh - qh + 7) * 15 + (kw - qw + 7)];
        }
    }

    float mx[4], sm[4];
#pragma unroll
    for (int a = 0; a < 4; a++)
        mx[a] = fmaxf(fmaxf(s[a][0], s[a][1]), fmaxf(s[a][2], s[a][3]));
#pragma unroll
    for (int off = 8; off; off >>= 1)
#pragma unroll
        for (int a = 0; a < 4; a++)
            mx[a] = fmaxf(mx[a], __shfl_xor_sync(0xffffffffu, mx[a], off));
#pragma unroll
    for (int a = 0; a < 4; a++) {
        sm[a] = 0.f;
#pragma unroll
        for (int b = 0; b < 4; b++) {
            s[a][b] = __expf(s[a][b] - mx[a]);
            sm[a] += s[a][b];
        }
    }
#pragma unroll
    for (int off = 8; off; off >>= 1)
#pragma unroll
        for (int a = 0; a < 4; a++)
            sm[a] += __shfl_xor_sync(0xffffffffu, sm[a], off);
    float inv[4];
#pragma unroll
    for (int a = 0; a < 4; a++) inv[a] = 1.f / sm[a];

#pragma unroll
    for (int b = 0; b < 4; b++) {
        float4 v = make_float4(s[0][b] * inv[0], s[1][b] * inv[1],
                               s[2][b] * inv[2], s[3][b] * inv[3]);
        *(float4*)&Pt[(tk * 4 + b) * 68 + tq * 4] = v;
    }
    __syncthreads();

    const int td = tid & 15;
    float o[4][2];
#pragma unroll
    for (int a = 0; a < 4; a++) { o[a][0] = 0.f; o[a][1] = 0.f; }
#pragma unroll 8
    for (int k = 0; k < 64; k++) {
        float4 pf = *(const float4*)&Pt[k * 68 + tq * 4];
        float2 vf = *(const float2*)&Vs[k * 36 + td * 2];
        const float* pa = (const float*)&pf;
#pragma unroll
        for (int a = 0; a < 4; a++) {
            o[a][0] = fmaf(pa[a], vf.x, o[a][0]);
            o[a][1] = fmaf(pa[a], vf.y, o[a][1]);
        }
    }
#pragma unroll
    for (int a = 0; a < 4; a++) {
        int q = tq * 4 + a;
        size_t ob = ((size_t)win * 64 + q) * (size_t)E_DIM + head * HD_ + td * 2;
        *(float2*)&out[ob] = make_float2(o[a][0], o[a][1]);
    }
}

// ---------------------------------------------------------------------------
// out[row] = LayerNorm(a[row] + b[row]) * g + be
// ---------------------------------------------------------------------------
__global__ void __launch_bounds__(128) add_ln_kernel(
    const float* __restrict__ A, const float* __restrict__ Bv,
    const float* __restrict__ g, const float* __restrict__ be,
    float* __restrict__ out)
{
    const int row = blockIdx.x;
    const int tid = threadIdx.x;
    size_t base = (size_t)row * E_DIM + tid * 4;

    float4 a = *(const float4*)(A + base);
    float4 b = *(const float4*)(Bv + base);
    float y0 = a.x + b.x, y1 = a.y + b.y, y2 = a.z + b.z, y3 = a.w + b.w;

    float s  = y0 + y1 + y2 + y3;
    float s2 = y0 * y0 + y1 * y1 + y2 * y2 + y3 * y3;
#pragma unroll
    for (int off = 16; off; off >>= 1) {
        s  += __shfl_down_sync(0xffffffffu, s, off);
        s2 += __shfl_down_sync(0xffffffffu, s2, off);
    }
    __shared__ float ss[4], ss2[4];
    int warp = tid >> 5, lane = tid & 31;
    if (lane == 0) { ss[warp] = s; ss2[warp] = s2; }
    __syncthreads();
    s  = ss[0] + ss[1] + ss[2] + ss[3];
    s2 = ss2[0] + ss2[1] + ss2[2] + ss2[3];

    const float rE = 1.f / 512.f;
    float mean = s * rE;
    float var  = s2 * rE - mean * mean;
    float rstd = rsqrtf(var + 1e-5f);

    int e = tid * 4;
    float4 gw = *(const float4*)(g + e);
    float4 bb = *(const float4*)(be + e);
    float4 o;
    o.x = (y0 - mean) * rstd * gw.x + bb.x;
    o.y = (y1 - mean) * rstd * gw.y + bb.y;
    o.z = (y2 - mean) * rstd * gw.z + bb.z;
    o.w = (y3 - mean) * rstd * gw.w + bb.w;
    *(float4*)(out + base) = o;
}

// ---------------------------------------------------------------------------
extern "C" void kernel_launch(void* const* d_in, const int* in_sizes, int n_in,
                              void* d_out, int out_size)
{
    const float* x     = (const float*)d_in[0];
    const float* w_qkv = (const float*)d_in[1];
    const float* b_qkv = (const float*)d_in[2];
    const float* w_out = (const float*)d_in[3];
    const float* b_out = (const float*)d_in[4];
    const float* pos   = (const float*)d_in[5];
    const float* w1    = (const float*)d_in[6];
    const float* b1    = (const float*)d_in[7];
    const float* w2    = (const float*)d_in[8];
    const float* b2    = (const float*)d_in[9];
    const float* ln1w  = (const float*)d_in[10];
    const float* ln1b  = (const float*)d_in[11];
    const float* ln2w  = (const float*)d_in[12];
    const float* ln2b  = (const float*)d_in[13];
    float* out = (float*)d_out;

    static float *p_qkv = nullptr, *p_attn = nullptr, *p_t0 = nullptr,
                 *p_z = nullptr, *p_h = nullptr;
    static bool inited = false;
    if (!inited) {
        cudaGetSymbolAddress((void**)&p_qkv,  g_qkv);
        cudaGetSymbolAddress((void**)&p_attn, g_attn);
        cudaGetSymbolAddress((void**)&p_t0,   g_t0);
        cudaGetSymbolAddress((void**)&p_z,    g_z);
        cudaGetSymbolAddress((void**)&p_h,    g_h);
        cudaFuncSetAttribute(gemm_tf32<0, 1>, cudaFuncAttributeMaxDynamicSharedMemorySize, GSM_BYTES);
        cudaFuncSetAttribute(gemm_tf32<0, 2>, cudaFuncAttributeMaxDynamicSharedMemorySize, GSM_BYTES);
        cudaFuncSetAttribute(gemm_tf32<1, 0>, cudaFuncAttributeMaxDynamicSharedMemorySize, GSM_BYTES);
        cudaFuncSetAttribute(gemm_tf32<0, 0>, cudaFuncAttributeMaxDynamicSharedMemorySize, GSM_BYTES);
        inited = true;
    }

    // 1. QKV projection -> window layout
    gemm_tf32<0, 1><<<dim3(QKV_N / 128, T_TOK / 128), 256, GSM_BYTES>>>(
        x, w_qkv, b_qkv, p_qkv, T_TOK, QKV_N, E_DIM);

    // 2. window attention
    attn_kernel<<<dim3(NWIN, NH_), 256>>>(p_qkv, pos, p_attn);

    // 3. output projection -> token layout
    gemm_tf32<0, 2><<<dim3(E_DIM / 128, T_TOK / 128), 256, GSM_BYTES>>>(
        p_attn, w_out, b_out, p_t0, T_TOK, E_DIM, E_DIM);

    // 4. residual + LN1
    add_ln_kernel<<<T_TOK, 128>>>(x, p_t0, ln1w, ln1b, p_z);

    // 5. FFN up + ReLU
    gemm_tf32<1, 0><<<dim3(DFF_N / 128, T_TOK / 128), 256, GSM_BYTES>>>(
        p_z, w1, b1, p_h, T_TOK, DFF_N, E_DIM);

    // 6. FFN down
    gemm_tf32<0, 0><<<dim3(E_DIM / 128, T_TOK / 128), 256, GSM_BYTES>>>(
        p_h, w2, b2, p_t0, T_TOK, E_DIM, DFF_N);

    // 7. residual + LN2 -> output
    add_ln_kernel<<<T_TOK, 128>>>(p_z, p_t0, ln2w, ln2b, out);
}

// round 10
// speedup vs baseline: 2.1040x; 2.1040x over previous
#include <cuda_runtime.h>
#include <cuda_bf16.h>
#include <cstdint>
#include <math.h>

// ---------------------------------------------------------------------------
// Swin Transformer encoder layer, GB300 round-10:
// R6 pipeline (BK=16, 4-stage cp.async, 128x128 CTA, 2 CTA/SM) but with
// 4 warps (2x2) x 64x64 warp tiles -> 33% less smem read duplication.
// ---------------------------------------------------------------------------

#define T_TOK   65536
#define E_DIM   512
#define QKV_N   1536
#define DFF_N   2048
#define NWIN    1024
#define NH_     16
#define HD_     32

__device__ float g_qkv[(size_t)T_TOK * QKV_N];
__device__ float g_attn[(size_t)T_TOK * E_DIM];
__device__ float g_t0[(size_t)T_TOK * E_DIM];
__device__ float g_z[(size_t)T_TOK * E_DIM];
__device__ float g_h[(size_t)T_TOK * DFF_N];

__device__ __forceinline__ int to_win_row(int m) {
    int b = m >> 14, p = m & 16383;
    int r = p >> 7, c = p & 127;
    int win = (b << 8) + ((r >> 3) << 4) + (c >> 3);
    int n   = ((r & 7) << 3) + (c & 7);
    return (win << 6) + n;
}
__device__ __forceinline__ int from_win_row(int m) {
    int win = m >> 6, n = m & 63;
    int b  = win >> 8, wi = win & 255;
    int wr = wi >> 4,  wc = wi & 15;
    int r = (wr << 3) + (n >> 3);
    int c = (wc << 3) + (n & 7);
    return (b << 14) + (r << 7) + c;
}

__device__ __forceinline__ void mma_tf32(float c[4], const uint32_t a[4], const uint32_t b[2]) {
    asm volatile(
        "mma.sync.aligned.m16n8k8.row.col.f32.tf32.tf32.f32 "
        "{%0,%1,%2,%3},{%4,%5,%6,%7},{%8,%9},{%0,%1,%2,%3};\n"
        : "+f"(c[0]), "+f"(c[1]), "+f"(c[2]), "+f"(c[3])
        : "r"(a[0]), "r"(a[1]), "r"(a[2]), "r"(a[3]), "r"(b[0]), "r"(b[1]));
}

__device__ __forceinline__ void ldsm4(uint32_t& r0, uint32_t& r1, uint32_t& r2, uint32_t& r3,
                                      uint32_t addr) {
    asm volatile("ldmatrix.sync.aligned.m8n8.x4.shared.b16 {%0,%1,%2,%3}, [%4];"
                 : "=r"(r0), "=r"(r1), "=r"(r2), "=r"(r3) : "r"(addr));
}

__device__ __forceinline__ void cpasync16(uint32_t dst, const float* src) {
    asm volatile("cp.async.cg.shared.global [%0], [%1], 16;" :: "r"(dst), "l"(src));
}
__device__ __forceinline__ void cp_commit() {
    asm volatile("cp.async.commit_group;" ::: "memory");
}
template <int N>
__device__ __forceinline__ void cp_wait() {
    asm volatile("cp.async.wait_group %0;" :: "n"(N) : "memory");
}

// ---------------------------------------------------------------------------
// TF32 NT GEMM: C[m][n] = sum_k A[m][k]*B[n][k] + bias[n].
// Block 128x128, BK=16, 128 threads = 4 warps (2m x 2n), warp tile 64x64.
// Smem: k-major 128x16 tiles, XOR swizzle (chunk ^= (row>>1)&3); 4-stage
// cp.async ring; ldmatrix.x4.b16 fragment reads; raw fp32 bits to tf32 mma.
// EPI: 0 bias, 1 bias+relu.  PERM: 0 none, 1 to_win, 2 from_win.
// ---------------------------------------------------------------------------
#define STAGES 4
#define GSM_BYTES (STAGES * 8192 * 2)

template <int EPI, int PERM>
__global__ void __launch_bounds__(128, 2) gemm_tf32(
    const float* __restrict__ A, const float* __restrict__ B,
    const float* __restrict__ bias, float* __restrict__ C,
    int M, int N, int K)
{
    extern __shared__ __align__(128) uint32_t smem[];
    const uint32_t asb = (uint32_t)__cvta_generic_to_shared(smem);
    const uint32_t bsb = asb + STAGES * 8192;

    const int tid  = threadIdx.x;
    const int lane = tid & 31;
    const int warp = tid >> 5;
    const int wr = warp >> 1;        // m half (64 rows)
    const int wc = warp & 1;         // n half (64 cols)
    const int bm = blockIdx.y << 7;
    const int bn = blockIdx.x << 7;

    // loader: thread -> base row = tid>>2 (0..31), chunk = tid&3; 4 row-groups
    const int lrow = tid >> 2;
    const int lk   = (tid & 3) << 2;
    const int sw   = (((lk >> 2) ^ ((lrow >> 1) & 3)) << 2);
    const uint32_t aoff0 = (uint32_t)(lrow * 16 + sw) * 4u;   // byte offset
    // row groups at +32 rows = +2048 bytes in smem

    const float* aP[4];
    const float* bP[4];
#pragma unroll
    for (int q = 0; q < 4; q++) {
        aP[q] = A + (size_t)(bm + lrow + 32 * q) * K + lk;
        bP[q] = B + (size_t)(bn + lrow + 32 * q) * K + lk;
    }

    // ldmatrix lane invariants
    const int lm   = (lane & 7) + (((lane >> 3) & 1) << 3);
    const int ahik = lane >> 4;
    const int amsw = (lm >> 1) & 3;
    const int brow = lane & 7;
    const int bnt2 = (lane >> 4) & 1;
    const int bhik = (lane >> 3) & 1;
    const int bmsw = (brow >> 1) & 3;

    float acc[4][8][4];
#pragma unroll
    for (int i = 0; i < 4; i++)
#pragma unroll
        for (int j = 0; j < 8; j++)
#pragma unroll
            for (int v = 0; v < 4; v++) acc[i][j][v] = 0.f;

    const int ntiles = K >> 4;

    // prologue: stages 0..2
#pragma unroll
    for (int s = 0; s < STAGES - 1; s++) {
        const int kk = s << 4;
        const uint32_t sa = asb + s * 8192;
        const uint32_t sb = bsb + s * 8192;
#pragma unroll
        for (int q = 0; q < 4; q++) {
            cpasync16(sa + aoff0 + q * 2048, aP[q] + kk);
            cpasync16(sb + aoff0 + q * 2048, bP[q] + kk);
        }
        cp_commit();
    }

    for (int t = 0; t < ntiles; t++) {
        cp_wait<STAGES - 2>();
        __syncthreads();

        if (t + STAGES - 1 < ntiles) {
            const int s = (t + STAGES - 1) & (STAGES - 1);
            const int kk = (t + STAGES - 1) << 4;
            const uint32_t sa = asb + s * 8192;
            const uint32_t sb = bsb + s * 8192;
#pragma unroll
            for (int q = 0; q < 4; q++) {
                cpasync16(sa + aoff0 + q * 2048, aP[q] + kk);
                cpasync16(sb + aoff0 + q * 2048, bP[q] + kk);
            }
            cp_commit();
        }

        const int cur = t & (STAGES - 1);
        const uint32_t abuf = asb + cur * 8192;
        const uint32_t bbuf = bsb + cur * 8192;
#pragma unroll
        for (int s = 0; s < 2; s++) {
            uint32_t afr[4][4];
#pragma unroll
            for (int i = 0; i < 4; i++) {
                int m = wr * 64 + i * 16 + lm;
                int chunk = (s * 2 + ahik) ^ amsw;
                ldsm4(afr[i][0], afr[i][1], afr[i][2], afr[i][3],
                      abuf + (uint32_t)(m * 16 + chunk * 4) * 4u);
            }
            uint32_t bfr[8][2];
#pragma unroll
            for (int jj = 0; jj < 4; jj++) {
                int ntile = wc * 8 + 2 * jj + bnt2;
                int n = ntile * 8 + brow;
                int chunk = (s * 2 + bhik) ^ bmsw;
                ldsm4(bfr[2 * jj][0], bfr[2 * jj][1], bfr[2 * jj + 1][0], bfr[2 * jj + 1][1],
                      bbuf + (uint32_t)(n * 16 + chunk * 4) * 4u);
            }
#pragma unroll
            for (int i = 0; i < 4; i++)
#pragma unroll
                for (int j = 0; j < 8; j++)
                    mma_tf32(acc[i][j], afr[i], bfr[j]);
        }
    }

    // epilogue
    const int r  = lane >> 2;
    const int cc = (lane & 3) << 1;
#pragma unroll
    for (int i = 0; i < 4; i++) {
        int row0 = bm + wr * 64 + i * 16 + r;
        int row1 = row0 + 8;
        int o0, o1;
        if (PERM == 0)      { o0 = row0;               o1 = row1; }
        else if (PERM == 1) { o0 = to_win_row(row0);   o1 = to_win_row(row1); }
        else                { o0 = from_win_row(row0); o1 = from_win_row(row1); }
#pragma unroll
        for (int j = 0; j < 8; j++) {
            int gn = bn + wc * 64 + j * 8 + cc;
            float b0 = bias[gn], b1 = bias[gn + 1];
            float v00 = acc[i][j][0] + b0, v01 = acc[i][j][1] + b1;
            float v10 = acc[i][j][2] + b0, v11 = acc[i][j][3] + b1;
            if (EPI == 1) {
                v00 = fmaxf(v00, 0.f); v01 = fmaxf(v01, 0.f);
                v10 = fmaxf(v10, 0.f); v11 = fmaxf(v11, 0.f);
            }
            *(float2*)&C[(size_t)o0 * N + gn] = make_float2(v00, v01);
            *(float2*)&C[(size_t)o1 * N + gn] = make_float2(v10, v11);
        }
    }
}

// ---------------------------------------------------------------------------
// Window attention: one block per (window, head). 4x4 register micro-tiles.
// ---------------------------------------------------------------------------
__global__ void __launch_bounds__(256) attn_kernel(
    const float* __restrict__ qkv, const float* __restrict__ pos_emb,
    float* __restrict__ out)
{
    const int win = blockIdx.x;
    const int head = blockIdx.y;
    const int tid = threadIdx.x;

    __shared__ float Qt[32 * 68];
    __shared__ float Kt[32 * 68];
    __shared__ float Vs[64 * 36];
    __shared__ float Pt[64 * 68];
    __shared__ float bias_s[225];

    {
        int n  = tid >> 2;
        int c0 = (tid & 3) << 3;
        size_t base = ((size_t)win * 64 + n) * (size_t)QKV_N + head * HD_ + c0;
        float4 a = *(const float4*)(qkv + base);
        float4 b = *(const float4*)(qkv + base + 4);
        Qt[(c0 + 0) * 68 + n] = a.x; Qt[(c0 + 1) * 68 + n] = a.y;
        Qt[(c0 + 2) * 68 + n] = a.z; Qt[(c0 + 3) * 68 + n] = a.w;
        Qt[(c0 + 4) * 68 + n] = b.x; Qt[(c0 + 5) * 68 + n] = b.y;
        Qt[(c0 + 6) * 68 + n] = b.z; Qt[(c0 + 7) * 68 + n] = b.w;
        a = *(const float4*)(qkv + base + 512);
        b = *(const float4*)(qkv + base + 516);
        Kt[(c0 + 0) * 68 + n] = a.x; Kt[(c0 + 1) * 68 + n] = a.y;
        Kt[(c0 + 2) * 68 + n] = a.z; Kt[(c0 + 3) * 68 + n] = a.w;
        Kt[(c0 + 4) * 68 + n] = b.x; Kt[(c0 + 5) * 68 + n] = b.y;
        Kt[(c0 + 6) * 68 + n] = b.z; Kt[(c0 + 7) * 68 + n] = b.w;
        a = *(const float4*)(qkv + base + 1024);
        b = *(const float4*)(qkv + base + 1028);
        *(float4*)&Vs[n * 36 + c0]     = a;
        *(float4*)&Vs[n * 36 + c0 + 4] = b;
    }
    if (tid < 225) bias_s[tid] = pos_emb[tid];
    __syncthreads();

    const int tq = tid >> 4;
    const int tk = tid & 15;

    float s[4][4];
#pragma unroll
    for (int a = 0; a < 4; a++)
#pragma unroll
        for (int b = 0; b < 4; b++) s[a][b] = 0.f;

#pragma unroll 8
    for (int d = 0; d < 32; d++) {
        float4 qf = *(const float4*)&Qt[d * 68 + tq * 4];
        float4 kf = *(const float4*)&Kt[d * 68 + tk * 4];
        const float* qa = (const float*)&qf;
        const float* ka = (const float*)&kf;
#pragma unroll
        for (int a = 0; a < 4; a++)
#pragma unroll
            for (int b = 0; b < 4; b++)
                s[a][b] = fmaf(qa[a], ka[b], s[a][b]);
    }

    const float scl = 0.17677669529663687f;
#pragma unroll
    for (int a = 0; a < 4; a++) {
        int q = tq * 4 + a, qh = q >> 3, qw = q & 7;
#pragma unroll
        for (int b = 0; b < 4; b++) {
            int k = tk * 4 + b, kh = k >> 3, kw = k & 7;
            s[a][b] = s[a][b] * scl + bias_s[(kh - qh + 7) * 15 + (kw - qw + 7)];
        }
    }

    float mx[4], sm[4];
#pragma unroll
    for (int a = 0; a < 4; a++)
        mx[a] = fmaxf(fmaxf(s[a][0], s[a][1]), fmaxf(s[a][2], s[a][3]));
#pragma unroll
    for (int off = 8; off; off >>= 1)
#pragma unroll
        for (int a = 0; a < 4; a++)
            mx[a] = fmaxf(mx[a], __shfl_xor_sync(0xffffffffu, mx[a], off));
#pragma unroll
    for (int a = 0; a < 4; a++) {
        sm[a] = 0.f;
#pragma unroll
        for (int b = 0; b < 4; b++) {
            s[a][b] = __expf(s[a][b] - mx[a]);
            sm[a] += s[a][b];
        }
    }
#pragma unroll
    for (int off = 8; off; off >>= 1)
#pragma unroll
        for (int a = 0; a < 4; a++)
            sm[a] += __shfl_xor_sync(0xffffffffu, sm[a], off);
    float inv[4];
#pragma unroll
    for (int a = 0; a < 4; a++) inv[a] = 1.f / sm[a];

#pragma unroll
    for (int b = 0; b < 4; b++) {
        float4 v = make_float4(s[0][b] * inv[0], s[1][b] * inv[1],
                               s[2][b] * inv[2], s[3][b] * inv[3]);
        *(float4*)&Pt[(tk * 4 + b) * 68 + tq * 4] = v;
    }
    __syncthreads();

    const int td = tid & 15;
    float o[4][2];
#pragma unroll
    for (int a = 0; a < 4; a++) { o[a][0] = 0.f; o[a][1] = 0.f; }
#pragma unroll 8
    for (int k = 0; k < 64; k++) {
        float4 pf = *(const float4*)&Pt[k * 68 + tq * 4];
        float2 vf = *(const float2*)&Vs[k * 36 + td * 2];
        const float* pa = (const float*)&pf;
#pragma unroll
        for (int a = 0; a < 4; a++) {
            o[a][0] = fmaf(pa[a], vf.x, o[a][0]);
            o[a][1] = fmaf(pa[a], vf.y, o[a][1]);
        }
    }
#pragma unroll
    for (int a = 0; a < 4; a++) {
        int q = tq * 4 + a;
        size_t ob = ((size_t)win * 64 + q) * (size_t)E_DIM + head * HD_ + td * 2;
        *(float2*)&out[ob] = make_float2(o[a][0], o[a][1]);
    }
}

// ---------------------------------------------------------------------------
// out[row] = LayerNorm(a[row] + b[row]) * g + be
// ---------------------------------------------------------------------------
__global__ void __launch_bounds__(128) add_ln_kernel(
    const float* __restrict__ A, const float* __restrict__ Bv,
    const float* __restrict__ g, const float* __restrict__ be,
    float* __restrict__ out)
{
    const int row = blockIdx.x;
    const int tid = threadIdx.x;
    size_t base = (size_t)row * E_DIM + tid * 4;

    float4 a = *(const float4*)(A + base);
    float4 b = *(const float4*)(Bv + base);
    float y0 = a.x + b.x, y1 = a.y + b.y, y2 = a.z + b.z, y3 = a.w + b.w;

    float s  = y0 + y1 + y2 + y3;
    float s2 = y0 * y0 + y1 * y1 + y2 * y2 + y3 * y3;
#pragma unroll
    for (int off = 16; off; off >>= 1) {
        s  += __shfl_down_sync(0xffffffffu, s, off);
        s2 += __shfl_down_sync(0xffffffffu, s2, off);
    }
    __shared__ float ss[4], ss2[4];
    int warp = tid >> 5, lane = tid & 31;
    if (lane == 0) { ss[warp] = s; ss2[warp] = s2; }
    __syncthreads();
    s  = ss[0] + ss[1] + ss[2] + ss[3];
    s2 = ss2[0] + ss2[1] + ss2[2] + ss2[3];

    const float rE = 1.f / 512.f;
    float mean = s * rE;
    float var  = s2 * rE - mean * mean;
    float rstd = rsqrtf(var + 1e-5f);

    int e = tid * 4;
    float4 gw = *(const float4*)(g + e);
    float4 bb = *(const float4*)(be + e);
    float4 o;
    o.x = (y0 - mean) * rstd * gw.x + bb.x;
    o.y = (y1 - mean) * rstd * gw.y + bb.y;
    o.z = (y2 - mean) * rstd * gw.z + bb.z;
    o.w = (y3 - mean) * rstd * gw.w + bb.w;
    *(float4*)(out + base) = o;
}

// ---------------------------------------------------------------------------
extern "C" void kernel_launch(void* const* d_in, const int* in_sizes, int n_in,
                              void* d_out, int out_size)
{
    const float* x     = (const float*)d_in[0];
    const float* w_qkv = (const float*)d_in[1];
    const float* b_qkv = (const float*)d_in[2];
    const float* w_out = (const float*)d_in[3];
    const float* b_out = (const float*)d_in[4];
    const float* pos   = (const float*)d_in[5];
    const float* w1    = (const float*)d_in[6];
    const float* b1    = (const float*)d_in[7];
    const float* w2    = (const float*)d_in[8];
    const float* b2    = (const float*)d_in[9];
    const float* ln1w  = (const float*)d_in[10];
    const float* ln1b  = (const float*)d_in[11];
    const float* ln2w  = (const float*)d_in[12];
    const float* ln2b  = (const float*)d_in[13];
    float* out = (float*)d_out;

    static float *p_qkv = nullptr, *p_attn = nullptr, *p_t0 = nullptr,
                 *p_z = nullptr, *p_h = nullptr;
    static bool inited = false;
    if (!inited) {
        cudaGetSymbolAddress((void**)&p_qkv,  g_qkv);
        cudaGetSymbolAddress((void**)&p_attn, g_attn);
        cudaGetSymbolAddress((void**)&p_t0,   g_t0);
        cudaGetSymbolAddress((void**)&p_z,    g_z);
        cudaGetSymbolAddress((void**)&p_h,    g_h);
        cudaFuncSetAttribute(gemm_tf32<0, 1>, cudaFuncAttributeMaxDynamicSharedMemorySize, GSM_BYTES);
        cudaFuncSetAttribute(gemm_tf32<0, 2>, cudaFuncAttributeMaxDynamicSharedMemorySize, GSM_BYTES);
        cudaFuncSetAttribute(gemm_tf32<1, 0>, cudaFuncAttributeMaxDynamicSharedMemorySize, GSM_BYTES);
        cudaFuncSetAttribute(gemm_tf32<0, 0>, cudaFuncAttributeMaxDynamicSharedMemorySize, GSM_BYTES);
        inited = true;
    }

    // 1. QKV projection -> window layout
    gemm_tf32<0, 1><<<dim3(QKV_N / 128, T_TOK / 128), 128, GSM_BYTES>>>(
        x, w_qkv, b_qkv, p_qkv, T_TOK, QKV_N, E_DIM);

    // 2. window attention
    attn_kernel<<<dim3(NWIN, NH_), 256>>>(p_qkv, pos, p_attn);

    // 3. output projection -> token layout
    gemm_tf32<0, 2><<<dim3(E_DIM / 128, T_TOK / 128), 128, GSM_BYTES>>>(
        p_attn, w_out, b_out, p_t0, T_TOK, E_DIM, E_DIM);

    // 4. residual + LN1
    add_ln_kernel<<<T_TOK, 128>>>(x, p_t0, ln1w, ln1b, p_z);

    // 5. FFN up + ReLU
    gemm_tf32<1, 0><<<dim3(DFF_N / 128, T_TOK / 128), 128, GSM_BYTES>>>(
        p_z, w1, b1, p_h, T_TOK, DFF_N, E_DIM);

    // 6. FFN down
    gemm_tf32<0, 0><<<dim3(E_DIM / 128, T_TOK / 128), 128, GSM_BYTES>>>(
        p_h, w2, b2, p_t0, T_TOK, E_DIM, DFF_N);

    // 7. residual + LN2 -> output
    add_ln_kernel<<<T_TOK, 128>>>(p_z, p_t0, ln2w, ln2b, out);
}